// round 2
// baseline (speedup 1.0000x reference)
#include <cuda_runtime.h>
#include <math.h>

#define TT   24
#define DD   3
#define UU   2
#define HH1  8
#define HH2  16
#define FC1O 128
#define ACTN 24
#define OBSW (DD*TT + UU)   // 74
#define FEATS (TT*HH2 + UU) // 386

// shared memory layout (float offsets)
#define SM_WIH1  0                       // 32x3   = 96
#define SM_WHH1  (SM_WIH1 + 96)          // 32x8   = 256
#define SM_B1    (SM_WHH1 + 256)         // 32
#define SM_WIH2  (SM_B1 + 32)            // 64x8   = 512
#define SM_WHH2  (SM_WIH2 + 512)         // 64x16  = 1024
#define SM_B2    (SM_WHH2 + 1024)        // 64
#define SM_FC1B  (SM_B2 + 64)            // 128
#define SM_FC2W  (SM_FC1B + 128)         // 24x128 = 3072
#define SM_FC2B  (SM_FC2W + 3072)        // 24
#define SM_FC1WT (SM_FC2B + 24)          // 386x128 = 49408 (transposed: [c][k])
#define SM_TOTAL (SM_FC1WT + 49408)      // 54616 floats = 218464 B

__device__ __forceinline__ float sigf(float x) {
    return __fdividef(1.0f, 1.0f + __expf(-x));
}
__device__ __forceinline__ float tanhf_fast(float x) {
    // tanh(x) = 1 - 2/(1+e^{2x}); saturates correctly for |x| large
    return 1.0f - __fdividef(2.0f, 1.0f + __expf(2.0f * x));
}

__global__ void __launch_bounds__(256, 1)
lstm_actor_kernel(const float* __restrict__ obs,
                  const float* __restrict__ w_ih1, const float* __restrict__ w_hh1,
                  const float* __restrict__ b_ih1, const float* __restrict__ b_hh1,
                  const float* __restrict__ w_ih2, const float* __restrict__ w_hh2,
                  const float* __restrict__ b_ih2, const float* __restrict__ b_hh2,
                  const float* __restrict__ fc1_w, const float* __restrict__ fc1_b,
                  const float* __restrict__ fc2_w, const float* __restrict__ fc2_b,
                  float* __restrict__ out, int B)
{
    extern __shared__ float sm[];
    const int tid = threadIdx.x;

    // ---- cooperative weight staging ----
    for (int i = tid; i < 96;   i += 256) sm[SM_WIH1 + i] = w_ih1[i];
    for (int i = tid; i < 256;  i += 256) sm[SM_WHH1 + i] = w_hh1[i];
    for (int i = tid; i < 32;   i += 256) sm[SM_B1   + i] = b_ih1[i] + b_hh1[i];
    for (int i = tid; i < 512;  i += 256) sm[SM_WIH2 + i] = w_ih2[i];
    for (int i = tid; i < 1024; i += 256) sm[SM_WHH2 + i] = w_hh2[i];
    for (int i = tid; i < 64;   i += 256) sm[SM_B2   + i] = b_ih2[i] + b_hh2[i];
    for (int i = tid; i < 128;  i += 256) sm[SM_FC1B + i] = fc1_b[i];
    for (int i = tid; i < 3072; i += 256) sm[SM_FC2W + i] = fc2_w[i];
    for (int i = tid; i < 24;   i += 256) sm[SM_FC2B + i] = fc2_b[i];
    // fc1_w [128][386] -> transposed [386][128]
    for (int i = tid; i < FC1O * FEATS; i += 256) {
        int k = i / FEATS;
        int c = i - k * FEATS;
        sm[SM_FC1WT + c * FC1O + k] = fc1_w[i];
    }
    __syncthreads();

    const int b = blockIdx.x * 256 + tid;
    if (b >= B) return;
    const float* row = obs + (size_t)b * OBSW;

    float h1[HH1], c1[HH1], h2[HH2], c2[HH2];
#pragma unroll
    for (int j = 0; j < HH1; j++) { h1[j] = 0.f; c1[j] = 0.f; }
#pragma unroll
    for (int j = 0; j < HH2; j++) { h2[j] = 0.f; c2[j] = 0.f; }

    float acc[FC1O];
#pragma unroll
    for (int k = 0; k < FC1O; k++) acc[k] = 0.f;

    for (int t = 0; t < TT; t++) {
        const float x0 = row[t];
        const float xA = row[TT + t];
        const float xB = row[2 * TT + t];

        // ---------------- LSTM layer 1 (H1=8) ----------------
        float h1n[HH1];
#pragma unroll
        for (int j = 0; j < HH1; j++) {
            float gi = sm[SM_B1 + j];
            float gf = sm[SM_B1 + HH1 + j];
            float gg = sm[SM_B1 + 2 * HH1 + j];
            float go = sm[SM_B1 + 3 * HH1 + j];
            // input projection (D=3)
            gi = fmaf(sm[SM_WIH1 + (j) * 3 + 0], x0, gi);
            gi = fmaf(sm[SM_WIH1 + (j) * 3 + 1], xA, gi);
            gi = fmaf(sm[SM_WIH1 + (j) * 3 + 2], xB, gi);
            gf = fmaf(sm[SM_WIH1 + (HH1 + j) * 3 + 0], x0, gf);
            gf = fmaf(sm[SM_WIH1 + (HH1 + j) * 3 + 1], xA, gf);
            gf = fmaf(sm[SM_WIH1 + (HH1 + j) * 3 + 2], xB, gf);
            gg = fmaf(sm[SM_WIH1 + (2 * HH1 + j) * 3 + 0], x0, gg);
            gg = fmaf(sm[SM_WIH1 + (2 * HH1 + j) * 3 + 1], xA, gg);
            gg = fmaf(sm[SM_WIH1 + (2 * HH1 + j) * 3 + 2], xB, gg);
            go = fmaf(sm[SM_WIH1 + (3 * HH1 + j) * 3 + 0], x0, go);
            go = fmaf(sm[SM_WIH1 + (3 * HH1 + j) * 3 + 1], xA, go);
            go = fmaf(sm[SM_WIH1 + (3 * HH1 + j) * 3 + 2], xB, go);
            // recurrent projection (H1=8)
#pragma unroll
            for (int r = 0; r < HH1; r++) {
                const float hv = h1[r];
                gi = fmaf(sm[SM_WHH1 + (j) * HH1 + r], hv, gi);
                gf = fmaf(sm[SM_WHH1 + (HH1 + j) * HH1 + r], hv, gf);
                gg = fmaf(sm[SM_WHH1 + (2 * HH1 + j) * HH1 + r], hv, gg);
                go = fmaf(sm[SM_WHH1 + (3 * HH1 + j) * HH1 + r], hv, go);
            }
            const float cn = sigf(gf) * c1[j] + sigf(gi) * tanhf_fast(gg);
            c1[j] = cn;
            h1n[j] = sigf(go) * tanhf_fast(cn);
        }
#pragma unroll
        for (int j = 0; j < HH1; j++) h1[j] = h1n[j];

        // ---------------- LSTM layer 2 (H2=16) ----------------
        float h2n[HH2];
#pragma unroll
        for (int j = 0; j < HH2; j++) {
            float gi = sm[SM_B2 + j];
            float gf = sm[SM_B2 + HH2 + j];
            float gg = sm[SM_B2 + 2 * HH2 + j];
            float go = sm[SM_B2 + 3 * HH2 + j];
#pragma unroll
            for (int r = 0; r < HH1; r++) {
                const float hv = h1[r];
                gi = fmaf(sm[SM_WIH2 + (j) * HH1 + r], hv, gi);
                gf = fmaf(sm[SM_WIH2 + (HH2 + j) * HH1 + r], hv, gf);
                gg = fmaf(sm[SM_WIH2 + (2 * HH2 + j) * HH1 + r], hv, gg);
                go = fmaf(sm[SM_WIH2 + (3 * HH2 + j) * HH1 + r], hv, go);
            }
#pragma unroll
            for (int r = 0; r < HH2; r++) {
                const float hv = h2[r];
                gi = fmaf(sm[SM_WHH2 + (j) * HH2 + r], hv, gi);
                gf = fmaf(sm[SM_WHH2 + (HH2 + j) * HH2 + r], hv, gf);
                gg = fmaf(sm[SM_WHH2 + (2 * HH2 + j) * HH2 + r], hv, gg);
                go = fmaf(sm[SM_WHH2 + (3 * HH2 + j) * HH2 + r], hv, go);
            }
            const float cn = sigf(gf) * c2[j] + sigf(gi) * tanhf_fast(gg);
            c2[j] = cn;
            h2n[j] = sigf(go) * tanhf_fast(cn);
        }

        // ------- FC1 incremental accumulation: acc += W1t[t*16+j][:] * h2n[j] -------
        const float4* wbase = (const float4*)&sm[SM_FC1WT + (t * HH2) * FC1O];
#pragma unroll
        for (int j = 0; j < HH2; j++) {
            const float hv = h2n[j];
#pragma unroll
            for (int k = 0; k < FC1O / 4; k++) {
                const float4 w = wbase[j * (FC1O / 4) + k];
                acc[4 * k + 0] = fmaf(w.x, hv, acc[4 * k + 0]);
                acc[4 * k + 1] = fmaf(w.y, hv, acc[4 * k + 1]);
                acc[4 * k + 2] = fmaf(w.z, hv, acc[4 * k + 2]);
                acc[4 * k + 3] = fmaf(w.w, hv, acc[4 * k + 3]);
            }
        }
#pragma unroll
        for (int j = 0; j < HH2; j++) h2[j] = h2n[j];
    }

    // ------- x2 tail of FC1, bias, ReLU -------
    {
        const float xu0 = row[DD * TT + 0];
        const float xu1 = row[DD * TT + 1];
        const float4* wu = (const float4*)&sm[SM_FC1WT + (TT * HH2) * FC1O];
#pragma unroll
        for (int k = 0; k < FC1O / 4; k++) {
            const float4 w0 = wu[k];
            const float4 w1 = wu[FC1O / 4 + k];
            acc[4 * k + 0] = fmaf(w0.x, xu0, fmaf(w1.x, xu1, acc[4 * k + 0]));
            acc[4 * k + 1] = fmaf(w0.y, xu0, fmaf(w1.y, xu1, acc[4 * k + 1]));
            acc[4 * k + 2] = fmaf(w0.z, xu0, fmaf(w1.z, xu1, acc[4 * k + 2]));
            acc[4 * k + 3] = fmaf(w0.w, xu0, fmaf(w1.w, xu1, acc[4 * k + 3]));
        }
#pragma unroll
        for (int k = 0; k < FC1O; k++)
            acc[k] = fmaxf(acc[k] + sm[SM_FC1B + k], 0.0f);
    }

    // ------- FC2 + softsign -------
    float res[ACTN];
#pragma unroll
    for (int a = 0; a < ACTN; a++) {
        const float4* w = (const float4*)&sm[SM_FC2W + a * FC1O];
        float s0 = 0.f, s1 = 0.f, s2 = 0.f, s3 = 0.f;
#pragma unroll
        for (int k = 0; k < FC1O / 4; k++) {
            const float4 wv = w[k];
            s0 = fmaf(wv.x, acc[4 * k + 0], s0);
            s1 = fmaf(wv.y, acc[4 * k + 1], s1);
            s2 = fmaf(wv.z, acc[4 * k + 2], s2);
            s3 = fmaf(wv.w, acc[4 * k + 3], s3);
        }
        const float s = sm[SM_FC2B + a] + ((s0 + s1) + (s2 + s3));
        res[a] = s / (1.0f + fabsf(s));
    }

    // coalesced-ish vector store: 24 floats = 96B, 16B-aligned per thread
    float4* outp = (float4*)(out + (size_t)b * ACTN);
#pragma unroll
    for (int a = 0; a < ACTN / 4; a++)
        outp[a] = make_float4(res[4 * a + 0], res[4 * a + 1], res[4 * a + 2], res[4 * a + 3]);
}

extern "C" void kernel_launch(void* const* d_in, const int* in_sizes, int n_in,
                              void* d_out, int out_size)
{
    const float* obs   = (const float*)d_in[0];
    const float* w_ih1 = (const float*)d_in[1];
    const float* w_hh1 = (const float*)d_in[2];
    const float* b_ih1 = (const float*)d_in[3];
    const float* b_hh1 = (const float*)d_in[4];
    const float* w_ih2 = (const float*)d_in[5];
    const float* w_hh2 = (const float*)d_in[6];
    const float* b_ih2 = (const float*)d_in[7];
    const float* b_hh2 = (const float*)d_in[8];
    const float* fc1_w = (const float*)d_in[9];
    const float* fc1_b = (const float*)d_in[10];
    const float* fc2_w = (const float*)d_in[11];
    const float* fc2_b = (const float*)d_in[12];
    float* out = (float*)d_out;

    const int B = in_sizes[0] / OBSW;
    const size_t smem = (size_t)SM_TOTAL * sizeof(float); // 218464 B

    cudaFuncSetAttribute(lstm_actor_kernel,
                         cudaFuncAttributeMaxDynamicSharedMemorySize, (int)smem);

    const int threads = 256;
    const int blocks = (B + threads - 1) / threads;
    lstm_actor_kernel<<<blocks, threads, smem>>>(
        obs, w_ih1, w_hh1, b_ih1, b_hh1, w_ih2, w_hh2, b_ih2, b_hh2,
        fc1_w, fc1_b, fc2_w, fc2_b, out, B);
}

// round 13
// speedup vs baseline: 4.3714x; 4.3714x over previous
#include <cuda_runtime.h>
#include <math.h>

#define TT   24
#define DD   3
#define UU   2
#define HH1  8
#define HH2  16
#define FC1O 128
#define ACTN 24
#define OBSW (DD*TT + UU)    // 74
#define HALF 64              // FC1 outputs per thread

typedef unsigned long long ull;

// ---------------- shared memory layout (float offsets) ----------------
#define SM_W1IF  0                        // 8j x 3d x2 = 48
#define SM_W1GO  (SM_W1IF + 48)           // 48
#define SM_R1IF  (SM_W1GO + 48)           // 8x8x2 = 128
#define SM_R1GO  (SM_R1IF + 128)          // 128
#define SM_B1IF  (SM_R1GO + 128)          // 16
#define SM_B1GO  (SM_B1IF + 16)           // 16
#define SM_W2IF  (SM_B1GO + 16)           // 16x8x2 = 256
#define SM_W2GO  (SM_W2IF + 256)          // 256
#define SM_R2IF  (SM_W2GO + 256)          // 16x16x2 = 512
#define SM_R2GO  (SM_R2IF + 512)          // 512
#define SM_B2IF  (SM_R2GO + 512)          // 32
#define SM_B2GO  (SM_B2IF + 32)           // 32
#define SM_FC1B  (SM_B2GO + 32)           // 128
#define SM_FC2B  (SM_FC1B + 128)          // 24 (+pad->32)
#define SM_FC2W  (SM_FC2B + 32)           // 2 half tables: 24x64 each + 4 skew
#define FC2_HSTRIDE (24*64 + 4)           // 1540 (16B skew between halves)
#define SM_FC1T  (SM_FC2W + 2*FC2_HSTRIDE)// 2 half tables: 386x64 each + 4 skew
#define FC1_HSTRIDE (386*64 + 4)          // 24708
#define SM_TOTAL (SM_FC1T + 2*FC1_HSTRIDE)// ~54708 floats = 218832 B

// ---------------- f32x2 helpers ----------------
__device__ __forceinline__ ull pack2(float lo, float hi) {
    ull r; asm("mov.b64 %0, {%1,%2};" : "=l"(r) : "f"(lo), "f"(hi)); return r;
}
__device__ __forceinline__ void unpack2(ull v, float& lo, float& hi) {
    asm("mov.b64 {%0,%1}, %2;" : "=f"(lo), "=f"(hi) : "l"(v));
}
__device__ __forceinline__ void fma2(ull& acc, ull a, ull b) {
    asm("fma.rn.f32x2 %0, %1, %2, %0;" : "+l"(acc) : "l"(a), "l"(b));
}
__device__ __forceinline__ float rcp_fast(float x) {
    float r; asm("rcp.approx.f32 %0, %1;" : "=f"(r) : "f"(x)); return r;
}
__device__ __forceinline__ float sigf(float x) {
    return rcp_fast(1.0f + __expf(-x));
}
__device__ __forceinline__ float tanhf_fast(float x) {
    // tanh(x) = 1 - 2/(1+e^{2x}); saturates correctly for |x| large
    return fmaf(-2.0f, rcp_fast(1.0f + __expf(2.0f * x)), 1.0f);
}

__global__ void __launch_bounds__(256, 1)
lstm_actor_kernel(const float* __restrict__ obs,
                  const float* __restrict__ w_ih1, const float* __restrict__ w_hh1,
                  const float* __restrict__ b_ih1, const float* __restrict__ b_hh1,
                  const float* __restrict__ w_ih2, const float* __restrict__ w_hh2,
                  const float* __restrict__ b_ih2, const float* __restrict__ b_hh2,
                  const float* __restrict__ fc1_w, const float* __restrict__ fc1_b,
                  const float* __restrict__ fc2_w, const float* __restrict__ fc2_b,
                  float* __restrict__ out, int B)
{
    extern __shared__ float sm[];
    const int tid = threadIdx.x;

    // ---------------- stage packed weight tables ----------------
    // Layer1 input: gates (i,f) and (g,o) interleaved as float2
    for (int i = tid; i < 24; i += 256) {
        int j = i / 3, d = i % 3;
        sm[SM_W1IF + 2*i]     = w_ih1[(j)      * 3 + d];
        sm[SM_W1IF + 2*i + 1] = w_ih1[(j + 8)  * 3 + d];
        sm[SM_W1GO + 2*i]     = w_ih1[(j + 16) * 3 + d];
        sm[SM_W1GO + 2*i + 1] = w_ih1[(j + 24) * 3 + d];
    }
    for (int i = tid; i < 64; i += 256) {
        int j = i / 8, r = i % 8;
        sm[SM_R1IF + 2*i]     = w_hh1[(j)      * 8 + r];
        sm[SM_R1IF + 2*i + 1] = w_hh1[(j + 8)  * 8 + r];
        sm[SM_R1GO + 2*i]     = w_hh1[(j + 16) * 8 + r];
        sm[SM_R1GO + 2*i + 1] = w_hh1[(j + 24) * 8 + r];
    }
    for (int i = tid; i < 8; i += 256) {
        sm[SM_B1IF + 2*i]     = b_ih1[i]      + b_hh1[i];
        sm[SM_B1IF + 2*i + 1] = b_ih1[i + 8]  + b_hh1[i + 8];
        sm[SM_B1GO + 2*i]     = b_ih1[i + 16] + b_hh1[i + 16];
        sm[SM_B1GO + 2*i + 1] = b_ih1[i + 24] + b_hh1[i + 24];
    }
    for (int i = tid; i < 128; i += 256) {
        int j = i / 8, r = i % 8;
        sm[SM_W2IF + 2*i]     = w_ih2[(j)      * 8 + r];
        sm[SM_W2IF + 2*i + 1] = w_ih2[(j + 16) * 8 + r];
        sm[SM_W2GO + 2*i]     = w_ih2[(j + 32) * 8 + r];
        sm[SM_W2GO + 2*i + 1] = w_ih2[(j + 48) * 8 + r];
    }
    for (int i = tid; i < 256; i += 256) {
        int j = i / 16, r = i % 16;
        sm[SM_R2IF + 2*i]     = w_hh2[(j)      * 16 + r];
        sm[SM_R2IF + 2*i + 1] = w_hh2[(j + 16) * 16 + r];
        sm[SM_R2GO + 2*i]     = w_hh2[(j + 32) * 16 + r];
        sm[SM_R2GO + 2*i + 1] = w_hh2[(j + 48) * 16 + r];
    }
    for (int i = tid; i < 16; i += 256) {
        sm[SM_B2IF + 2*i]     = b_ih2[i]      + b_hh2[i];
        sm[SM_B2IF + 2*i + 1] = b_ih2[i + 16] + b_hh2[i + 16];
        sm[SM_B2GO + 2*i]     = b_ih2[i + 32] + b_hh2[i + 32];
        sm[SM_B2GO + 2*i + 1] = b_ih2[i + 48] + b_hh2[i + 48];
    }
    for (int i = tid; i < 128; i += 256) sm[SM_FC1B + i] = fc1_b[i];
    for (int i = tid; i < 24;  i += 256) sm[SM_FC2B + i] = fc2_b[i];
    // FC2 weights, half-split with 16B skew: table[h][a][kk] = fc2_w[a*128 + h*64 + kk]
    for (int i = tid; i < 2 * 24 * 64; i += 256) {
        int h = i / (24 * 64), rem = i % (24 * 64);
        int a = rem / 64, kk = rem % 64;
        sm[SM_FC2W + h * FC2_HSTRIDE + a * 64 + kk] = fc2_w[a * 128 + h * 64 + kk];
    }
    // FC1 weights transposed + half-split with 16B skew:
    // table[h][c][kk] = fc1_w[(h*64+kk)*386 + c]
    for (int i = tid; i < 2 * 386 * 64; i += 256) {
        int h = i / (386 * 64), rem = i % (386 * 64);
        int c = rem / 64, kk = rem % 64;
        sm[SM_FC1T + h * FC1_HSTRIDE + c * 64 + kk] = fc1_w[(h * 64 + kk) * 386 + c];
    }
    __syncthreads();

    // ---------------- sample mapping: 2 threads per sample ----------------
    const int lane = tid & 31;
    const int half = lane >> 4;           // 0: FC1 cols 0-63, 1: cols 64-127
    int s = blockIdx.x * 128 + (tid >> 5) * 16 + (lane & 15);
    const bool valid = (s < B);
    if (!valid) s = B - 1;                // clamp: keep warp converged for shfl
    const float* row = obs + (size_t)s * OBSW;

    ull  h1d[HH1];  float c1[HH1];
    ull  h2d[HH2];  float c2[HH2];
    ull  acc[HALF / 2];
#pragma unroll
    for (int j = 0; j < HH1; j++) { h1d[j] = 0ull; c1[j] = 0.f; }
#pragma unroll
    for (int j = 0; j < HH2; j++) { h2d[j] = 0ull; c2[j] = 0.f; }
#pragma unroll
    for (int k = 0; k < HALF / 2; k++) acc[k] = 0ull;

    const float* fc1base = &sm[SM_FC1T + half * FC1_HSTRIDE];

    for (int t = 0; t < TT; t++) {
        const float x0 = __ldg(row + t);
        const float xA = __ldg(row + TT + t);
        const float xB = __ldg(row + 2 * TT + t);
        const ull xx0 = pack2(x0, x0), xxA = pack2(xA, xA), xxB = pack2(xB, xB);

        // -------- LSTM layer 1 (H1=8), gates packed (i,f) / (g,o) --------
        float h1n[HH1];
#pragma unroll
        for (int j = 0; j < HH1; j++) {
            ull gif = *(const ull*)&sm[SM_B1IF + 2 * j];
            ull ggo = *(const ull*)&sm[SM_B1GO + 2 * j];
            fma2(gif, *(const ull*)&sm[SM_W1IF + 2 * (j * 3 + 0)], xx0);
            fma2(gif, *(const ull*)&sm[SM_W1IF + 2 * (j * 3 + 1)], xxA);
            fma2(gif, *(const ull*)&sm[SM_W1IF + 2 * (j * 3 + 2)], xxB);
            fma2(ggo, *(const ull*)&sm[SM_W1GO + 2 * (j * 3 + 0)], xx0);
            fma2(ggo, *(const ull*)&sm[SM_W1GO + 2 * (j * 3 + 1)], xxA);
            fma2(ggo, *(const ull*)&sm[SM_W1GO + 2 * (j * 3 + 2)], xxB);
#pragma unroll
            for (int r = 0; r < HH1; r++) {
                fma2(gif, *(const ull*)&sm[SM_R1IF + 2 * (j * 8 + r)], h1d[r]);
                fma2(ggo, *(const ull*)&sm[SM_R1GO + 2 * (j * 8 + r)], h1d[r]);
            }
            float gi, gf, gg, go;
            unpack2(gif, gi, gf);
            unpack2(ggo, gg, go);
            const float cn = sigf(gf) * c1[j] + sigf(gi) * tanhf_fast(gg);
            c1[j] = cn;
            h1n[j] = sigf(go) * tanhf_fast(cn);
        }
#pragma unroll
        for (int j = 0; j < HH1; j++) h1d[j] = pack2(h1n[j], h1n[j]);

        // -------- LSTM layer 2 (H2=16) --------
        float h2n[HH2];
#pragma unroll
        for (int j = 0; j < HH2; j++) {
            ull gif = *(const ull*)&sm[SM_B2IF + 2 * j];
            ull ggo = *(const ull*)&sm[SM_B2GO + 2 * j];
#pragma unroll
            for (int r = 0; r < HH1; r++) {
                fma2(gif, *(const ull*)&sm[SM_W2IF + 2 * (j * 8 + r)], h1d[r]);
                fma2(ggo, *(const ull*)&sm[SM_W2GO + 2 * (j * 8 + r)], h1d[r]);
            }
#pragma unroll
            for (int r = 0; r < HH2; r++) {
                fma2(gif, *(const ull*)&sm[SM_R2IF + 2 * (j * 16 + r)], h2d[r]);
                fma2(ggo, *(const ull*)&sm[SM_R2GO + 2 * (j * 16 + r)], h2d[r]);
            }
            float gi, gf, gg, go;
            unpack2(gif, gi, gf);
            unpack2(ggo, gg, go);
            const float cn = sigf(gf) * c2[j] + sigf(gi) * tanhf_fast(gg);
            c2[j] = cn;
            h2n[j] = sigf(go) * tanhf_fast(cn);
        }

        // -------- FC1 incremental accumulation (this thread's 64 cols) --------
        const float* rowb = fc1base + (t * HH2) * HALF;
#pragma unroll
        for (int j = 0; j < HH2; j++) {
            const ull hvv = pack2(h2n[j], h2n[j]);
            h2d[j] = hvv;  // update packed recurrent state (layer2 loop is done)
            const ulonglong2* wp = (const ulonglong2*)(rowb + j * HALF);
#pragma unroll
            for (int k = 0; k < HALF / 4; k++) {
                const ulonglong2 w = wp[k];
                fma2(acc[2 * k],     w.x, hvv);
                fma2(acc[2 * k + 1], w.y, hvv);
            }
        }
    }

    // -------- x2 tail of FC1 --------
    {
        const float xu0 = __ldg(row + DD * TT + 0);
        const float xu1 = __ldg(row + DD * TT + 1);
        const ull u0 = pack2(xu0, xu0), u1 = pack2(xu1, xu1);
        const ulonglong2* w0 = (const ulonglong2*)(fc1base + (TT * HH2) * HALF);
        const ulonglong2* w1 = (const ulonglong2*)(fc1base + (TT * HH2 + 1) * HALF);
#pragma unroll
        for (int k = 0; k < HALF / 4; k++) {
            const ulonglong2 a0 = w0[k], a1 = w1[k];
            fma2(acc[2 * k],     a0.x, u0);
            fma2(acc[2 * k + 1], a0.y, u0);
            fma2(acc[2 * k],     a1.x, u1);
            fma2(acc[2 * k + 1], a1.y, u1);
        }
    }

    // -------- bias + ReLU (unpack/repack) --------
    {
        const float* fb = &sm[SM_FC1B + half * HALF];
#pragma unroll
        for (int k = 0; k < HALF / 2; k++) {
            float a0, a1;
            unpack2(acc[k], a0, a1);
            a0 = fmaxf(a0 + fb[2 * k], 0.0f);
            a1 = fmaxf(a1 + fb[2 * k + 1], 0.0f);
            acc[k] = pack2(a0, a1);
        }
    }

    // -------- FC2 (partial over this half) + pair-combine + softsign --------
    float res[ACTN];
    const ull* w2base = (const ull*)&sm[SM_FC2W + half * FC2_HSTRIDE];
#pragma unroll
    for (int a = 0; a < ACTN; a++) {
        ull ps = 0ull;
        const ull* w = w2base + a * (HALF / 2);
#pragma unroll
        for (int k = 0; k < HALF / 2; k++) fma2(ps, w[k], acc[k]);
        float s0, s1;
        unpack2(ps, s0, s1);
        float part = s0 + s1;
        float tot = part + __shfl_xor_sync(0xffffffffu, part, 16);
        tot += sm[SM_FC2B + a];
        res[a] = tot * rcp_fast(1.0f + fabsf(tot));
    }

    // -------- store: each half writes 12 floats (3 float4s) --------
    if (valid) {
        float4* outp = (float4*)(out + (size_t)s * ACTN + half * 12);
        const int o = half * 12;
#pragma unroll
        for (int q = 0; q < 3; q++)
            outp[q] = make_float4(res[o + 4 * q + 0], res[o + 4 * q + 1],
                                  res[o + 4 * q + 2], res[o + 4 * q + 3]);
    }
}

extern "C" void kernel_launch(void* const* d_in, const int* in_sizes, int n_in,
                              void* d_out, int out_size)
{
    const float* obs   = (const float*)d_in[0];
    const float* w_ih1 = (const float*)d_in[1];
    const float* w_hh1 = (const float*)d_in[2];
    const float* b_ih1 = (const float*)d_in[3];
    const float* b_hh1 = (const float*)d_in[4];
    const float* w_ih2 = (const float*)d_in[5];
    const float* w_hh2 = (const float*)d_in[6];
    const float* b_ih2 = (const float*)d_in[7];
    const float* b_hh2 = (const float*)d_in[8];
    const float* fc1_w = (const float*)d_in[9];
    const float* fc1_b = (const float*)d_in[10];
    const float* fc2_w = (const float*)d_in[11];
    const float* fc2_b = (const float*)d_in[12];
    float* out = (float*)d_out;

    const int B = in_sizes[0] / OBSW;
    const size_t smem = (size_t)SM_TOTAL * sizeof(float);

    cudaFuncSetAttribute(lstm_actor_kernel,
                         cudaFuncAttributeMaxDynamicSharedMemorySize, (int)smem);

    // 128 samples per block (2 threads/sample, 256 threads)
    const int blocks = (B + 127) / 128;
    lstm_actor_kernel<<<blocks, 256, smem>>>(
        obs, w_ih1, w_hh1, b_ih1, b_hh1, w_ih2, w_hh2, b_ih2, b_hh2,
        fc1_w, fc1_b, fc2_w, fc2_b, out, B);
}